// round 17
// baseline (speedup 1.0000x reference)
#include <cuda_runtime.h>

// Problem constants (fixed by the reference)
#define NN   10000
#define FIN  50
#define HID  512
#define FOUT 121
#define NE   160000

// ---------------- scratch (static device globals: no allocation) ----------------
__device__ int   g_edges[2 * NE];
__device__ int   g_is64;
__device__ int   g_cnt [NN];
__device__ int   g_fill[NN];
__device__ int   g_off [NN + 1];
__device__ int   g_csr [NE];
__device__ float g_agg1[NN * FIN];
__device__ float g_h   [NN * HID];
__device__ float g_p   [NN * FOUT];

// ---------------- edge dtype detection + conversion ----------------
__global__ void k_detect(const int* __restrict__ ei_raw) {
    __shared__ int nz;
    if (threadIdx.x == 0) nz = 0;
    __syncthreads();
    int local = 0;
    for (int i = threadIdx.x; i < 1024; i += blockDim.x)
        if (ei_raw[2 * i + 1] != 0) local = 1;
    if (local) atomicOr(&nz, 1);
    __syncthreads();
    if (threadIdx.x == 0) g_is64 = (nz == 0) ? 1 : 0;
}

__global__ void k_convert(const void* __restrict__ ei_raw) {
    int i = blockIdx.x * blockDim.x + threadIdx.x;
    if (i < 2 * NE) {
        int v;
        if (g_is64) v = (int)((const long long*)ei_raw)[i];
        else        v = ((const int*)ei_raw)[i];
        g_edges[i] = v;
    }
}

// ---------------- CSR build: histogram -> scan -> fill ----------------
__global__ void k_zero2() {
    int i = blockIdx.x * blockDim.x + threadIdx.x;
    if (i < NN) { g_cnt[i] = 0; g_fill[i] = 0; }
}

__global__ void k_hist() {
    int e = blockIdx.x * blockDim.x + threadIdx.x;
    if (e < NE) {
        int d = g_edges[NE + e];
        if ((unsigned)d < NN) atomicAdd(&g_cnt[d], 1);
    }
}

__global__ void k_scan() {
    __shared__ int tmp[1024];
    const int t = threadIdx.x;
    const int idx0 = t * 10;
    int local[10];
    int part = 0;
#pragma unroll
    for (int j = 0; j < 10; j++) {
        int idx = idx0 + j;
        int c = (idx < NN) ? g_cnt[idx] : 0;
        local[j] = c;
        part += c;
    }
    tmp[t] = part;
    __syncthreads();
    for (int off = 1; off < 1024; off <<= 1) {
        int v = (t >= off) ? tmp[t - off] : 0;
        __syncthreads();
        tmp[t] += v;
        __syncthreads();
    }
    int excl = tmp[t] - part;
#pragma unroll
    for (int j = 0; j < 10; j++) {
        int idx = idx0 + j;
        if (idx < NN) g_off[idx] = excl;
        excl += local[j];
    }
    if (t == 1023) g_off[NN] = tmp[1023];
}

__global__ void k_fill() {
    int e = blockIdx.x * blockDim.x + threadIdx.x;
    if (e < NE) {
        int s = g_edges[e];
        int d = g_edges[NE + e];
        if ((unsigned)s < NN && (unsigned)d < NN) {
            int pos = g_off[d] + atomicAdd(&g_fill[d], 1);
            g_csr[pos] = s;
        }
    }
}

// ---------------- gather aggregations (no atomics) ----------------
__global__ void k_agg1(const float* __restrict__ x) {
    int gid  = blockIdx.x * blockDim.x + threadIdx.x;
    int w    = gid >> 5;
    int lane = gid & 31;
    if (w >= NN) return;
    int b = g_off[w], e = g_off[w + 1];
    float s0 = 0.0f, s1 = 0.0f;
    for (int i = b; i < e; i++) {
        int src = g_csr[i];
        const float* row = x + (long)src * FIN;
        s0 += row[lane];
        if (lane + 32 < FIN) s1 += row[lane + 32];
    }
    float inv = 1.0f / fmaxf((float)(e - b), 1.0f);
    g_agg1[w * FIN + lane] = s0 * inv;
    if (lane + 32 < FIN) g_agg1[w * FIN + lane + 32] = s1 * inv;
}

__global__ void k_agg2(float* __restrict__ out) {
    int gid  = blockIdx.x * blockDim.x + threadIdx.x;
    int w    = gid >> 5;
    int lane = gid & 31;
    if (w >= NN) return;
    int b = g_off[w], e = g_off[w + 1];
    float s0 = 0.0f, s1 = 0.0f, s2 = 0.0f, s3 = 0.0f;
    for (int i = b; i < e; i++) {
        int src = g_csr[i];
        const float* row = g_p + (long)src * FOUT;
        s0 += row[lane];
        s1 += row[lane + 32];
        s2 += row[lane + 64];
        if (lane + 96 < FOUT) s3 += row[lane + 96];
    }
    float inv = 1.0f / fmaxf((float)(e - b), 1.0f);
    float* orow = out + (long)w * FOUT;
    orow[lane]      += s0 * inv;
    orow[lane + 32] += s1 * inv;
    orow[lane + 64] += s2 * inv;
    if (lane + 96 < FOUT) orow[lane + 96] += s3 * inv;
}

// ---------------- fp32 tiled GEMM, dual-A (layer 1) — unchanged ----------------
__global__ __launch_bounds__(256)
void gemm1_k(const float* __restrict__ A1, const float* __restrict__ W1,
             const float* __restrict__ A2, const float* __restrict__ W2,
             const float* __restrict__ bias, float* __restrict__ C,
             int M, int N, int K)
{
    constexpr int BM = 64, BN = 64, BK = 16, TM = 4, TN = 4;
    __shared__ float sA1[BK][BM];
    __shared__ float sW1[BK][BN];
    __shared__ float sA2[BK][BM];
    __shared__ float sW2[BK][BN];

    const int tid = threadIdx.x;
    const int tx = tid % 16;
    const int ty = tid / 16;
    const int m0 = blockIdx.y * BM;
    const int n0 = blockIdx.x * BN;

    float acc[TM][TN];
#pragma unroll
    for (int i = 0; i < TM; i++)
#pragma unroll
        for (int j = 0; j < TN; j++) acc[i][j] = 0.0f;

    const int arow = tid / 4;
    const int ac0  = (tid % 4) * 4;
    const int wcol = tid % 64;
    const int wr0  = tid / 64;

    for (int k0 = 0; k0 < K; k0 += BK) {
#pragma unroll
        for (int i = 0; i < 4; i++) {
            int k = k0 + ac0 + i;
            int m = m0 + arow;
            float v1 = 0.0f, v2 = 0.0f;
            if (m < M && k < K) {
                v1 = A1[(long)m * K + k];
                v2 = A2[(long)m * K + k];
            }
            sA1[ac0 + i][arow] = v1;
            sA2[ac0 + i][arow] = v2;
        }
#pragma unroll
        for (int it = 0; it < 4; it++) {
            int kr = wr0 + it * 4;
            int k = k0 + kr;
            int n = n0 + wcol;
            float v1 = 0.0f, v2 = 0.0f;
            if (k < K && n < N) {
                v1 = W1[(long)k * N + n];
                v2 = W2[(long)k * N + n];
            }
            sW1[kr][wcol] = v1;
            sW2[kr][wcol] = v2;
        }
        __syncthreads();

#pragma unroll
        for (int kk = 0; kk < BK; kk++) {
            float a1[TM], w1[TN], a2[TM], w2[TN];
#pragma unroll
            for (int i = 0; i < TM; i++) {
                a1[i] = sA1[kk][ty * TM + i];
                a2[i] = sA2[kk][ty * TM + i];
            }
#pragma unroll
            for (int j = 0; j < TN; j++) {
                w1[j] = sW1[kk][tx * TN + j];
                w2[j] = sW2[kk][tx * TN + j];
            }
#pragma unroll
            for (int i = 0; i < TM; i++)
#pragma unroll
                for (int j = 0; j < TN; j++) {
                    acc[i][j] += a1[i] * w1[j];
                    acc[i][j] += a2[i] * w2[j];
                }
        }
        __syncthreads();
    }

#pragma unroll
    for (int i = 0; i < TM; i++) {
        int m = m0 + ty * TM + i;
        if (m >= M) continue;
#pragma unroll
        for (int j = 0; j < TN; j++) {
            int n = n0 + tx * TN + j;
            if (n >= N) continue;
            float v = acc[i][j] + bias[n];
            C[(long)m * N + n] = fmaxf(v, 0.0f);
        }
    }
}

// ---------------- fp32 dual-B GEMM (layer 2): BM=128/TM=8, float4 smem, dbl-buffer ----
// C1 = A@Wa, C2 = A@Wb + bias. K multiple of 16 (K=512). Per kk: 64 FFMA + 4 LDS.128.
__global__ __launch_bounds__(256)
void gemm2_k(const float* __restrict__ A,
             const float* __restrict__ Wa, const float* __restrict__ Wb,
             const float* __restrict__ bias,
             float* __restrict__ C1, float* __restrict__ C2,
             int M, int N, int K)
{
    constexpr int BM = 128, BN = 64, BK = 16, TM = 8, TN = 4;
    __shared__ __align__(16) float sA [2][BK][BM];
    __shared__ __align__(16) float sWa[2][BK][BN];
    __shared__ __align__(16) float sWb[2][BK][BN];

    const int tid = threadIdx.x;
    const int tx = tid % 16;          // N: 16 x 4 = 64
    const int ty = tid / 16;          // M: 16 x 8 = 128
    const int m0 = blockIdx.y * BM;
    const int n0 = blockIdx.x * BN;

    float acc1[TM][TN], acc2[TM][TN];
#pragma unroll
    for (int i = 0; i < TM; i++)
#pragma unroll
        for (int j = 0; j < TN; j++) { acc1[i][j] = 0.0f; acc2[i][j] = 0.0f; }

    const int arow = tid >> 1;           // 0..127
    const int ac0  = (tid & 1) * 8;      // 0 or 8 (two float4s)
    const int am   = m0 + arow;
    const bool aok = (am < M);
    const int wcol = tid % 64;
    const int wr0  = tid / 64;           // 0..3
    const int wn   = n0 + wcol;
    const bool wok = (wn < N);
    const int nk = K / BK;

    // preload tile 0
    {
        float4 va0 = make_float4(0.f,0.f,0.f,0.f), va1 = va0;
        if (aok) {
            va0 = *(const float4*)(A + (long)am * K + ac0);
            va1 = *(const float4*)(A + (long)am * K + ac0 + 4);
        }
        sA[0][ac0+0][arow]=va0.x; sA[0][ac0+1][arow]=va0.y;
        sA[0][ac0+2][arow]=va0.z; sA[0][ac0+3][arow]=va0.w;
        sA[0][ac0+4][arow]=va1.x; sA[0][ac0+5][arow]=va1.y;
        sA[0][ac0+6][arow]=va1.z; sA[0][ac0+7][arow]=va1.w;
#pragma unroll
        for (int it = 0; it < 4; it++) {
            int kr = wr0 + it * 4;
            float va2 = 0.f, vb2 = 0.f;
            if (wok) {
                va2 = Wa[(long)kr * N + wn];
                vb2 = Wb[(long)kr * N + wn];
            }
            sWa[0][kr][wcol] = va2;
            sWb[0][kr][wcol] = vb2;
        }
    }
    __syncthreads();

    int buf = 0;
    for (int kt = 0; kt < nk; kt++) {
        float4 pa0 = make_float4(0.f,0.f,0.f,0.f), pa1 = pa0;
        float pwa[4], pwb[4];
        const bool more = (kt + 1 < nk);
        if (more) {
            const int k0n = (kt + 1) * BK;
            if (aok) {
                pa0 = *(const float4*)(A + (long)am * K + k0n + ac0);
                pa1 = *(const float4*)(A + (long)am * K + k0n + ac0 + 4);
            }
#pragma unroll
            for (int it = 0; it < 4; it++) {
                int kr = wr0 + it * 4;
                float va2 = 0.f, vb2 = 0.f;
                if (wok) {
                    va2 = Wa[(long)(k0n + kr) * N + wn];
                    vb2 = Wb[(long)(k0n + kr) * N + wn];
                }
                pwa[it] = va2;
                pwb[it] = vb2;
            }
        }

#pragma unroll
        for (int kk = 0; kk < BK; kk++) {
            const float4 a0 = *(const float4*)&sA[buf][kk][ty * TM];
            const float4 a1 = *(const float4*)&sA[buf][kk][ty * TM + 4];
            const float4 wa = *(const float4*)&sWa[buf][kk][tx * TN];
            const float4 wb = *(const float4*)&sWb[buf][kk][tx * TN];
            const float a[TM] = {a0.x, a0.y, a0.z, a0.w, a1.x, a1.y, a1.z, a1.w};
            const float waf[TN] = {wa.x, wa.y, wa.z, wa.w};
            const float wbf[TN] = {wb.x, wb.y, wb.z, wb.w};
#pragma unroll
            for (int i = 0; i < TM; i++)
#pragma unroll
                for (int j = 0; j < TN; j++) {
                    acc1[i][j] += a[i] * waf[j];
                    acc2[i][j] += a[i] * wbf[j];
                }
        }

        if (more) {
            const int nb = buf ^ 1;
            sA[nb][ac0+0][arow]=pa0.x; sA[nb][ac0+1][arow]=pa0.y;
            sA[nb][ac0+2][arow]=pa0.z; sA[nb][ac0+3][arow]=pa0.w;
            sA[nb][ac0+4][arow]=pa1.x; sA[nb][ac0+5][arow]=pa1.y;
            sA[nb][ac0+6][arow]=pa1.z; sA[nb][ac0+7][arow]=pa1.w;
#pragma unroll
            for (int it = 0; it < 4; it++) {
                int kr = wr0 + it * 4;
                sWa[nb][kr][wcol] = pwa[it];
                sWb[nb][kr][wcol] = pwb[it];
            }
        }
        __syncthreads();
        buf ^= 1;
    }

#pragma unroll
    for (int i = 0; i < TM; i++) {
        int m = m0 + ty * TM + i;
        if (m >= M) continue;
#pragma unroll
        for (int j = 0; j < TN; j++) {
            int n = n0 + tx * TN + j;
            if (n >= N) continue;
            C1[(long)m * N + n] = acc1[i][j];
            C2[(long)m * N + n] = acc2[i][j] + bias[n];
        }
    }
}

// ---------------- launch ----------------
extern "C" void kernel_launch(void* const* d_in, const int* in_sizes, int n_in,
                              void* d_out, int out_size)
{
    const float* x   = (const float*)d_in[0];
    const void*  ei  = d_in[1];
    const float* W1l = (const float*)d_in[2];
    const float* W1r = (const float*)d_in[3];
    const float* b1  = (const float*)d_in[4];
    const float* W2l = (const float*)d_in[5];
    const float* W2r = (const float*)d_in[6];
    const float* b2  = (const float*)d_in[7];
    float*       out = (float*)d_out;

    float *p_agg1, *p_h, *p_p;
    cudaGetSymbolAddress((void**)&p_agg1, g_agg1);
    cudaGetSymbolAddress((void**)&p_h,    g_h);
    cudaGetSymbolAddress((void**)&p_p,    g_p);

    // edge dtype detect + convert to int32
    k_detect<<<1, 256>>>((const int*)ei);
    k_convert<<<(2 * NE + 255) / 256, 256>>>(ei);

    // CSR by destination: histogram -> exclusive scan -> bucket fill
    k_zero2<<<(NN + 255) / 256, 256>>>();
    k_hist<<<(NE + 255) / 256, 256>>>();
    k_scan<<<1, 1024>>>();
    k_fill<<<(NE + 255) / 256, 256>>>();

    // layer 1: gather-mean of x (warp per dst), fused dual-A GEMM + bias + relu
    k_agg1<<<(NN * 32 + 255) / 256, 256>>>(x);
    {
        dim3 grid((HID + 63) / 64, (NN + 63) / 64);
        gemm1_k<<<grid, 256>>>(p_agg1, W1l, x, W1r, b1, p_h, NN, HID, FIN);
    }

    // layer 2: fused dual-B GEMM (BM=128/TM=8, double-buffered), then gather-mean
    {
        dim3 grid((FOUT + 63) / 64, (NN + 127) / 128);
        gemm2_k<<<grid, 256>>>(p_h, W2l, W2r, b2, p_p, out, NN, FOUT, HID);
        k_agg2<<<(NN * 32 + 255) / 256, 256>>>(out);
    }
}